// round 14
// baseline (speedup 1.0000x reference)
#include <cuda_runtime.h>
#include <cuda_fp16.h>
#include <cstdint>
#include <math.h>

#define SEQ    2048
#define HIDDEN 4096
#define NH     32
#define HD     128
#define NKV    8
#define QKVD   6144
#define KOFF   4096
#define VOFF   5120
#define KB     4096    // all GEMM operands: fp16 hi only, K = 4096
#define BK     64
#define STAGES 3
#define ROWB   144
#define STAGE_BYTES (128 * ROWB * 2)
#define B_OFF  (128 * ROWB)
// attention smem layout: Q + 3 KV buffers
#define AROW   272
#define Q_BYTES (128 * AROW)
#define KV_BYTES (64 * AROW)
#define ATTN_SMEM (Q_BYTES + 3 * (2 * KV_BYTES))  // 139264

// ---------------- scratch (__device__ globals; no allocs allowed) ----------
__device__ float  g_qkv [SEQ * QKVD];
__device__ __half g_A1  [SEQ * KB];
__device__ __half g_A2  [SEQ * KB];
__device__ __half g_Bqkv[QKVD * KB];
__device__ __half g_Bo  [HIDDEN * KB];
__device__ __half g_q16 [NH  * SEQ * HD];
__device__ __half g_k16 [NKV * SEQ * HD];
__device__ __half g_v16 [NKV * SEQ * HD];

__device__ __forceinline__ uint32_t smem_u32(const void* p) {
    uint32_t a;
    asm("{ .reg .u64 t; cvta.to.shared.u64 t, %1; cvt.u32.u64 %0, t; }" : "=r"(a) : "l"(p));
    return a;
}
#define CP_ASYNC16(dst, src) \
    asm volatile("cp.async.cg.shared.global [%0], [%1], 16;" :: "r"(dst), "l"(src) : "memory")

__device__ __forceinline__ void ldsm_x4(uint32_t* r, uint32_t addr) {
    asm volatile("ldmatrix.sync.aligned.m8n8.x4.shared.b16 {%0,%1,%2,%3}, [%4];"
                 : "=r"(r[0]), "=r"(r[1]), "=r"(r[2]), "=r"(r[3]) : "r"(addr));
}
__device__ __forceinline__ void ldsm_x4t(uint32_t* r, uint32_t addr) {
    asm volatile("ldmatrix.sync.aligned.m8n8.x4.trans.shared.b16 {%0,%1,%2,%3}, [%4];"
                 : "=r"(r[0]), "=r"(r[1]), "=r"(r[2]), "=r"(r[3]) : "r"(addr));
}
__device__ __forceinline__ void mma16816(float* d, const uint32_t* a, const uint32_t* b) {
    asm volatile(
        "mma.sync.aligned.m16n8k16.row.col.f32.f16.f16.f32 "
        "{%0,%1,%2,%3}, {%4,%5,%6,%7}, {%8,%9}, {%0,%1,%2,%3};"
        : "+f"(d[0]), "+f"(d[1]), "+f"(d[2]), "+f"(d[3])
        : "r"(a[0]), "r"(a[1]), "r"(a[2]), "r"(a[3]), "r"(b[0]), "r"(b[1]));
}
__device__ __forceinline__ uint32_t pack_h2(float a, float b) {
    __half2 h = __floats2half2_rn(a, b);
    return *(uint32_t*)&h;
}

// ---------------------------------------------------------------------------
// fp16 GEMM: C[M,N] = A[M,KB] @ Bt[N,KB]^T  (64 k-iterations)
// CTA 128x128, 128 threads = 4 warps (2x2) of 64x64 tiles, BK=64,
// 3-stage lookahead-2 cp.async pipeline, fragment double-buffering, 2 CTA/SM.
// ---------------------------------------------------------------------------
__global__ __launch_bounds__(128, 2) void gemm_mma_kernel(
    const __half* __restrict__ A,
    const __half* __restrict__ Bt,
    float* __restrict__ C, int N)
{
    extern __shared__ char smem[];
    const uint32_t sb = smem_u32(smem);
    const int tid = threadIdx.x;
    const int lane = tid & 31, warp = tid >> 5;
    const int wm = warp >> 1, wn = warp & 1;      // 2 x 2 warp grid, 64x64 tiles
    const int mbase = blockIdx.y * 128;
    const int nbase = blockIdx.x * 128;
    const int nIter = KB / BK;   // 64

    const __half* Arow = A  + (size_t)mbase * KB;
    const __half* Brow = Bt + (size_t)nbase * KB;

    // cp.async: each of 128 threads owns one A row and one B row (8 chunks each)
    auto load_stage = [&](int itL, int stL) {
        const int kb = itL * BK;
        const uint32_t base = sb + stL * STAGE_BYTES;
        const char* asrc = (const char*)(Arow + (size_t)tid * KB + kb);
        const char* bsrc = (const char*)(Brow + (size_t)tid * KB + kb);
#pragma unroll
        for (int ch = 0; ch < 8; ch++) {
            CP_ASYNC16(base + tid * ROWB + ch * 16,         asrc + ch * 16);
            CP_ASYNC16(base + B_OFF + tid * ROWB + ch * 16, bsrc + ch * 16);
        }
    };

    float acc[4][8][4];
#pragma unroll
    for (int i = 0; i < 4; i++)
#pragma unroll
        for (int j = 0; j < 8; j++)
#pragma unroll
            for (int r = 0; r < 4; r++) acc[i][j][r] = 0.f;

    load_stage(0, 0);
    asm volatile("cp.async.commit_group;" ::: "memory");
    load_stage(1, 1);
    asm volatile("cp.async.commit_group;" ::: "memory");

    const uint32_t a_row  = wm * 64 + (lane & 15);
    const uint32_t a_kc   = (lane >> 4);
    const uint32_t b_row0 = wn * 64 + (lane & 7);
    const uint32_t b_half = (lane >> 4) & 1;
    const uint32_t b_kc   = (lane >> 3) & 1;

    uint32_t af[2][4][4], bf[2][4][4];

    auto load_frags = [&](uint32_t abase, uint32_t bbase, int s, int buf) {
#pragma unroll
        for (int i = 0; i < 4; i++)
            ldsm_x4(af[buf][i], abase + (a_row + i * 16) * ROWB + (s * 2 + a_kc) * 16);
#pragma unroll
        for (int jj = 0; jj < 4; jj++)
            ldsm_x4(bf[buf][jj], bbase + (b_row0 + (2 * jj + b_half) * 8) * ROWB
                                 + (s * 2 + b_kc) * 16);
    };

    for (int it = 0; it < nIter; it++) {
        const int st = it % 3;
        if (it < nIter - 1) asm volatile("cp.async.wait_group 1;" ::: "memory");
        else                asm volatile("cp.async.wait_group 0;" ::: "memory");
        __syncthreads();
        if (it + 2 < nIter) {
            load_stage(it + 2, (it + 2) % 3);
            asm volatile("cp.async.commit_group;" ::: "memory");
        }

        const uint32_t abase = sb + st * STAGE_BYTES;
        const uint32_t bbase = abase + B_OFF;

        load_frags(abase, bbase, 0, 0);
#pragma unroll
        for (int s = 0; s < 4; s++) {
            if (s < 3) load_frags(abase, bbase, s + 1, (s + 1) & 1);
            const int buf = s & 1;
#pragma unroll
            for (int i = 0; i < 4; i++)
#pragma unroll
                for (int jj = 0; jj < 4; jj++) {
                    mma16816(acc[i][2 * jj],     af[buf][i], bf[buf][jj]);
                    mma16816(acc[i][2 * jj + 1], af[buf][i], bf[buf][jj] + 2);
                }
        }
    }

    const int g = lane >> 2, t = lane & 3;
#pragma unroll
    for (int i = 0; i < 4; i++) {
#pragma unroll
        for (int j = 0; j < 8; j++) {
            int row = mbase + wm * 64 + i * 16 + g;
            int col = nbase + wn * 64 + j * 8 + 2 * t;
            *(float2*)&C[(size_t)row * N + col] =
                make_float2(acc[i][j][0], acc[i][j][1]);
            *(float2*)&C[(size_t)(row + 8) * N + col] =
                make_float2(acc[i][j][2], acc[i][j][3]);
        }
    }
}

// ---------------------------------------------------------------------------
// fp32 -> fp16 convert (hi only): X[M,4096] -> Y[M,4096]
// ---------------------------------------------------------------------------
__global__ __launch_bounds__(256) void cvt_kernel(
    const float* __restrict__ X, __half* __restrict__ Y, int total)
{
    int idx = blockIdx.x * blockDim.x + threadIdx.x;
    if (idx >= total) return;
    Y[idx] = __float2half(X[idx]);
}

// ---------------------------------------------------------------------------
// W [4096, N] -> Bt [N, 4096] fp16 hi, tiled transpose.
// ---------------------------------------------------------------------------
__global__ __launch_bounds__(1024) void tsplit_kernel(
    const float* __restrict__ W, __half* __restrict__ Bt, int N)
{
    __shared__ float t[32][33];
    int n0 = blockIdx.x * 32, k0 = blockIdx.y * 32;
    t[threadIdx.y][threadIdx.x] = W[(size_t)(k0 + threadIdx.y) * N + n0 + threadIdx.x];
    __syncthreads();
    float x = t[threadIdx.x][threadIdx.y];
    int n = n0 + threadIdx.y, k = k0 + threadIdx.x;
    Bt[(size_t)n * KB + k] = __float2half(x);
}

// ---------------------------------------------------------------------------
// Fused RoPE + fp16 pack: g_qkv -> g_q16/g_k16/g_v16 (Q gets 1/sqrt(HD)).
// ---------------------------------------------------------------------------
__global__ __launch_bounds__(256) void pack_rope_kernel(const int* __restrict__ pos32)
{
    int idx = blockIdx.x * blockDim.x + threadIdx.x;
    if (idx >= SEQ * QKVD) return;
    int d  = idx & 127;
    int hh = (idx >> 7) % 48;
    int s  = idx / QKVD;

    if (hh < 40) {
        int base = s * QKVD + ((hh < 32) ? hh * HD : KOFF + (hh - 32) * HD);
        float v;
        if (d < 64) {
            int j = d & 31;
            bool is64 = (pos32[1] == 0);
            int posi = is64 ? pos32[2 * s] : pos32[s];
            float inv_freq = 1.0f / powf(10000.0f, (float)j * (1.0f / 32.0f));
            float fr = (float)posi * inv_freq;
            float cs, sn;
            sincosf(fr, &sn, &cs);
            float x1 = g_qkv[base + j];
            float x2 = g_qkv[base + 32 + j];
            v = (d < 32) ? (x1 * cs - x2 * sn) : (x2 * cs + x1 * sn);
        } else {
            v = g_qkv[base + d];
        }
        if (hh < 32)
            g_q16[((size_t)hh * SEQ + s) * HD + d] = __float2half(v * 0.088388347648318447f);
        else
            g_k16[((size_t)(hh - 32) * SEQ + s) * HD + d] = __float2half(v);
    } else {
        int kvh = hh - 40;
        float v = g_qkv[s * QKVD + VOFF + kvh * HD + d];
        g_v16[((size_t)kvh * SEQ + s) * HD + d] = __float2half(v);
    }
}

// ---------------------------------------------------------------------------
// Flash attention on mma.sync fp16 (passing, unchanged from R12).
// ---------------------------------------------------------------------------
__global__ __launch_bounds__(256) void attn_mma_kernel()
{
    extern __shared__ char smem[];
    const uint32_t sb = smem_u32(smem);
    const uint32_t Qs = sb;
    const int tid = threadIdx.x, lane = tid & 31, warp = tid >> 5;
    const int g = lane >> 2, t4 = lane & 3;
    const int qt = gridDim.x - 1 - (int)blockIdx.x;
    const int h = blockIdx.y, kvh = h >> 2;
    const int qbase = qt * 128;
    const int qrw = warp * 16;
    const int ntiles = qt * 2 + 2;

    const __half* q16 = g_q16 + (size_t)h   * SEQ * HD;
    const __half* k16 = g_k16 + (size_t)kvh * SEQ * HD;
    const __half* v16 = g_v16 + (size_t)kvh * SEQ * HD;

    auto load_kv = [&](int tt) {
        const int buf = tt % 3;
        const uint32_t Kb = sb + Q_BYTES + buf * (2 * KV_BYTES);
        const uint32_t Vb = Kb + KV_BYTES;
        const int kb = tt * 64;
#pragma unroll
        for (int i = 0; i < 4; i++) {
            int c = tid + 256 * i;
            int row = c >> 4, ch = c & 15;
            CP_ASYNC16(Kb + row * AROW + ch * 16,
                       (const char*)(k16 + (size_t)(kb + row) * HD) + ch * 16);
            CP_ASYNC16(Vb + row * AROW + ch * 16,
                       (const char*)(v16 + (size_t)(kb + row) * HD) + ch * 16);
        }
    };

#pragma unroll
    for (int i = 0; i < 8; i++) {
        int c = tid + 256 * i;
        int row = c >> 4, ch = c & 15;
        CP_ASYNC16(Qs + row * AROW + ch * 16,
                   (const char*)(q16 + (size_t)(qbase + row) * HD) + ch * 16);
    }
    load_kv(0);
    asm volatile("cp.async.commit_group;" ::: "memory");
    load_kv(1);
    asm volatile("cp.async.commit_group;" ::: "memory");

    float of[16][4];
#pragma unroll
    for (int i = 0; i < 16; i++)
#pragma unroll
        for (int r = 0; r < 4; r++) of[i][r] = 0.f;
    float m0 = -INFINITY, m1 = -INFINITY, l0 = 0.f, l1 = 0.f;

    const int row0 = qbase + qrw + g;

    for (int tt = 0; tt < ntiles; tt++) {
        if (tt < ntiles - 1) asm volatile("cp.async.wait_group 1;" ::: "memory");
        else                 asm volatile("cp.async.wait_group 0;" ::: "memory");
        __syncthreads();
        if (tt + 2 < ntiles) {
            load_kv(tt + 2);
            asm volatile("cp.async.commit_group;" ::: "memory");
        }

        const int kb = tt * 64;
        const uint32_t Kb = sb + Q_BYTES + (tt % 3) * (2 * KV_BYTES);
        const uint32_t Vb = Kb + KV_BYTES;

        float sf[8][4];
#pragma unroll
        for (int j = 0; j < 8; j++)
#pragma unroll
            for (int r = 0; r < 4; r++) sf[j][r] = 0.f;
#pragma unroll
        for (int s = 0; s < 8; s++) {
            uint32_t qf[4];
            ldsm_x4(qf, Qs + (qrw + (lane & 15)) * AROW + (s * 2 + (lane >> 4)) * 16);
#pragma unroll
            for (int jj = 0; jj < 4; jj++) {
                uint32_t kr[4];
                int brow = (lane & 7) + (2 * jj + ((lane >> 4) & 1)) * 8;
                ldsm_x4(kr, Kb + brow * AROW + (s * 2 + ((lane >> 3) & 1)) * 16);
                mma16816(sf[2 * jj],     qf, kr);
                mma16816(sf[2 * jj + 1], qf, kr + 2);
            }
        }

        if (kb + 63 > qbase + qrw) {
#pragma unroll
            for (int j = 0; j < 8; j++) {
                int c0 = kb + j * 8 + 2 * t4;
                if (c0     > row0)     sf[j][0] = -INFINITY;
                if (c0 + 1 > row0)     sf[j][1] = -INFINITY;
                if (c0     > row0 + 8) sf[j][2] = -INFINITY;
                if (c0 + 1 > row0 + 8) sf[j][3] = -INFINITY;
            }
        }

        float mt0 = -INFINITY, mt1 = -INFINITY;
#pragma unroll
        for (int j = 0; j < 8; j++) {
            mt0 = fmaxf(mt0, fmaxf(sf[j][0], sf[j][1]));
            mt1 = fmaxf(mt1, fmaxf(sf[j][2], sf[j][3]));
        }
        mt0 = fmaxf(mt0, __shfl_xor_sync(0xffffffffu, mt0, 1));
        mt0 = fmaxf(mt0, __shfl_xor_sync(0xffffffffu, mt0, 2));
        mt1 = fmaxf(mt1, __shfl_xor_sync(0xffffffffu, mt1, 1));
        mt1 = fmaxf(mt1, __shfl_xor_sync(0xffffffffu, mt1, 2));
        float mn0 = fmaxf(m0, mt0), mn1 = fmaxf(m1, mt1);
        float a0 = __expf(m0 - mn0), a1 = __expf(m1 - mn1);
        float s0 = 0.f, s1 = 0.f;
#pragma unroll
        for (int j = 0; j < 8; j++) {
            sf[j][0] = __expf(sf[j][0] - mn0);
            sf[j][1] = __expf(sf[j][1] - mn0);
            sf[j][2] = __expf(sf[j][2] - mn1);
            sf[j][3] = __expf(sf[j][3] - mn1);
            s0 += sf[j][0] + sf[j][1];
            s1 += sf[j][2] + sf[j][3];
        }
        s0 += __shfl_xor_sync(0xffffffffu, s0, 1);
        s0 += __shfl_xor_sync(0xffffffffu, s0, 2);
        s1 += __shfl_xor_sync(0xffffffffu, s1, 1);
        s1 += __shfl_xor_sync(0xffffffffu, s1, 2);
        l0 = l0 * a0 + s0; l1 = l1 * a1 + s1;
        m0 = mn0; m1 = mn1;
#pragma unroll
        for (int i = 0; i < 16; i++) {
            of[i][0] *= a0; of[i][1] *= a0;
            of[i][2] *= a1; of[i][3] *= a1;
        }

#pragma unroll
        for (int c = 0; c < 4; c++) {
            uint32_t af[4];
            af[0] = pack_h2(sf[2 * c][0],     sf[2 * c][1]);
            af[1] = pack_h2(sf[2 * c][2],     sf[2 * c][3]);
            af[2] = pack_h2(sf[2 * c + 1][0], sf[2 * c + 1][1]);
            af[3] = pack_h2(sf[2 * c + 1][2], sf[2 * c + 1][3]);
#pragma unroll
            for (int d2 = 0; d2 < 8; d2++) {
                uint32_t vr[4];
                ldsm_x4t(vr, Vb + (16 * c + (lane & 15)) * AROW
                              + d2 * 32 + ((lane >> 4) & 1) * 16);
                mma16816(of[2 * d2],     af, vr);
                mma16816(of[2 * d2 + 1], af, vr + 2);
            }
        }
    }

    const float inv0 = 1.f / l0, inv1 = 1.f / l1;
#pragma unroll
    for (int dt = 0; dt < 16; dt++) {
        int col = h * HD + dt * 8 + 2 * t4;
        *(__half2*)&g_A2[(size_t)row0 * KB + col] =
            __floats2half2_rn(of[dt][0] * inv0, of[dt][1] * inv0);
        *(__half2*)&g_A2[(size_t)(row0 + 8) * KB + col] =
            __floats2half2_rn(of[dt][2] * inv1, of[dt][3] * inv1);
    }
}

// ---------------------------------------------------------------------------
extern "C" void kernel_launch(void* const* d_in, const int* in_sizes, int n_in,
                              void* d_out, int out_size)
{
    const float* hidden    = (const float*)d_in[0];
    const float* Wqkv      = (const float*)d_in[1];
    const float* Wo        = (const float*)d_in[2];
    const int*   positions = (const int*)d_in[3];
    float*       out       = (float*)d_out;

    float* qkv_ptr;
    __half *A1, *A2, *Bqkv, *Bo;
    cudaGetSymbolAddress((void**)&qkv_ptr, g_qkv);
    cudaGetSymbolAddress((void**)&A1,   g_A1);
    cudaGetSymbolAddress((void**)&A2,   g_A2);
    cudaGetSymbolAddress((void**)&Bqkv, g_Bqkv);
    cudaGetSymbolAddress((void**)&Bo,   g_Bo);

    const int gemm_smem = STAGES * STAGE_BYTES;   // 110592
    cudaFuncSetAttribute(gemm_mma_kernel, cudaFuncAttributeMaxDynamicSharedMemorySize, gemm_smem);
    cudaFuncSetAttribute(attn_mma_kernel, cudaFuncAttributeMaxDynamicSharedMemorySize, ATTN_SMEM);

    // operand conversion (all hi-only)
    cvt_kernel<<<(SEQ * HIDDEN) / 256, 256>>>(hidden, A1, SEQ * HIDDEN);
    tsplit_kernel<<<dim3(QKVD / 32, HIDDEN / 32), dim3(32, 32)>>>(Wqkv, Bqkv, QKVD);
    tsplit_kernel<<<dim3(HIDDEN / 32, HIDDEN / 32), dim3(32, 32)>>>(Wo, Bo, HIDDEN);

    // 1) QKV projection (K = 4096)
    gemm_mma_kernel<<<dim3(QKVD / 128, SEQ / 128), 128, gemm_smem>>>(A1, Bqkv, qkv_ptr, QKVD);
    // 2) fused RoPE + fp16 pack (q scaled)
    pack_rope_kernel<<<(SEQ * QKVD) / 256, 256>>>(positions);
    // 3) tensor-core flash attention -> g_A2 (fp16)
    attn_mma_kernel<<<dim3(SEQ / 128, NH), 256, ATTN_SMEM>>>();
    // 4) output projection (K = 4096)
    gemm_mma_kernel<<<dim3(HIDDEN / 128, SEQ / 128), 128, gemm_smem>>>(A2, Bo, out, HIDDEN);
}

// round 15
// speedup vs baseline: 1.7586x; 1.7586x over previous
#include <cuda_runtime.h>
#include <cuda_fp16.h>
#include <cstdint>
#include <math.h>

#define SEQ    2048
#define HIDDEN 4096
#define NH     32
#define HD     128
#define NKV    8
#define QKVD   6144
#define KOFF   4096
#define VOFF   5120
#define KB     4096    // all GEMM operands: fp16 hi only, K = 4096
#define BK     64
#define STAGES 3
#define ROWB   144
#define STAGE_BYTES (128 * ROWB * 2)
#define B_OFF  (128 * ROWB)
// attention smem layout: Q + 3 KV buffers
#define AROW   272
#define Q_BYTES (128 * AROW)
#define KV_BYTES (64 * AROW)
#define ATTN_SMEM (Q_BYTES + 3 * (2 * KV_BYTES))  // 139264

// ---------------- scratch (__device__ globals; no allocs allowed) ----------
__device__ float  g_qkv [SEQ * QKVD];
__device__ __half g_A1  [SEQ * KB];
__device__ __half g_A2  [SEQ * KB];
__device__ __half g_Bqkv[QKVD * KB];
__device__ __half g_Bo  [HIDDEN * KB];
__device__ __half g_q16 [NH  * SEQ * HD];
__device__ __half g_k16 [NKV * SEQ * HD];
__device__ __half g_v16 [NKV * SEQ * HD];
__device__ float2 g_rope[SEQ * 32];        // (cos, sin) per (s, j)

__device__ __forceinline__ uint32_t smem_u32(const void* p) {
    uint32_t a;
    asm("{ .reg .u64 t; cvta.to.shared.u64 t, %1; cvt.u32.u64 %0, t; }" : "=r"(a) : "l"(p));
    return a;
}
#define CP_ASYNC16(dst, src) \
    asm volatile("cp.async.cg.shared.global [%0], [%1], 16;" :: "r"(dst), "l"(src) : "memory")

__device__ __forceinline__ void ldsm_x4(uint32_t* r, uint32_t addr) {
    asm volatile("ldmatrix.sync.aligned.m8n8.x4.shared.b16 {%0,%1,%2,%3}, [%4];"
                 : "=r"(r[0]), "=r"(r[1]), "=r"(r[2]), "=r"(r[3]) : "r"(addr));
}
__device__ __forceinline__ void ldsm_x4t(uint32_t* r, uint32_t addr) {
    asm volatile("ldmatrix.sync.aligned.m8n8.x4.trans.shared.b16 {%0,%1,%2,%3}, [%4];"
                 : "=r"(r[0]), "=r"(r[1]), "=r"(r[2]), "=r"(r[3]) : "r"(addr));
}
__device__ __forceinline__ void mma16816(float* d, const uint32_t* a, const uint32_t* b) {
    asm volatile(
        "mma.sync.aligned.m16n8k16.row.col.f32.f16.f16.f32 "
        "{%0,%1,%2,%3}, {%4,%5,%6,%7}, {%8,%9}, {%0,%1,%2,%3};"
        : "+f"(d[0]), "+f"(d[1]), "+f"(d[2]), "+f"(d[3])
        : "r"(a[0]), "r"(a[1]), "r"(a[2]), "r"(a[3]), "r"(b[0]), "r"(b[1]));
}
__device__ __forceinline__ uint32_t pack_h2(float a, float b) {
    __half2 h = __floats2half2_rn(a, b);
    return *(uint32_t*)&h;
}

// ---------------------------------------------------------------------------
// fp16 GEMM (R12 version — best measured): C[M,N] = A[M,KB] @ Bt[N,KB]^T
// BM=BN=128, BK=64, 256 threads (8 warps, 2x4, 64x32 tiles), 3-stage
// lookahead-2 cp.async, ONE __syncthreads per iteration, 2 CTA/SM.
// ---------------------------------------------------------------------------
__global__ __launch_bounds__(256, 2) void gemm_mma_kernel(
    const __half* __restrict__ A,
    const __half* __restrict__ Bt,
    float* __restrict__ C, int N)
{
    extern __shared__ char smem[];
    const uint32_t sb = smem_u32(smem);
    const int tid = threadIdx.x;
    const int lane = tid & 31, warp = tid >> 5;
    const int wm = warp >> 2, wn = warp & 3;
    const int mbase = blockIdx.y * 128;
    const int nbase = blockIdx.x * 128;
    const int nIter = KB / BK;   // 64

    const __half* Arow = A  + (size_t)mbase * KB;
    const __half* Brow = Bt + (size_t)nbase * KB;

    const int c_row = tid >> 1;
    const int c_ch0 = (tid & 1) * 4;

    auto load_stage = [&](int itL, int stL) {
        const int kb = itL * BK;
        const uint32_t base = sb + stL * STAGE_BYTES;
        const char* asrc = (const char*)(Arow + (size_t)c_row * KB + kb);
        const char* bsrc = (const char*)(Brow + (size_t)c_row * KB + kb);
#pragma unroll
        for (int c = 0; c < 4; c++) {
            int ch = c_ch0 + c;
            CP_ASYNC16(base + c_row * ROWB + ch * 16,         asrc + ch * 16);
            CP_ASYNC16(base + B_OFF + c_row * ROWB + ch * 16, bsrc + ch * 16);
        }
    };

    float acc[4][4][4];
#pragma unroll
    for (int i = 0; i < 4; i++)
#pragma unroll
        for (int j = 0; j < 4; j++)
#pragma unroll
            for (int r = 0; r < 4; r++) acc[i][j][r] = 0.f;

    load_stage(0, 0);
    asm volatile("cp.async.commit_group;" ::: "memory");
    load_stage(1, 1);
    asm volatile("cp.async.commit_group;" ::: "memory");

    const uint32_t a_row = wm * 64 + (lane & 15);
    const uint32_t a_kc  = (lane >> 4);
    const uint32_t b_row0 = wn * 32 + (lane & 7);
    const uint32_t b_half = (lane >> 4) & 1;
    const uint32_t b_kc   = (lane >> 3) & 1;

    for (int it = 0; it < nIter; it++) {
        const int st = it % 3;
        if (it < nIter - 1) asm volatile("cp.async.wait_group 1;" ::: "memory");
        else                asm volatile("cp.async.wait_group 0;" ::: "memory");
        __syncthreads();
        if (it + 2 < nIter) {
            load_stage(it + 2, (it + 2) % 3);
            asm volatile("cp.async.commit_group;" ::: "memory");
        }

        const uint32_t abase = sb + st * STAGE_BYTES;
        const uint32_t bbase = abase + B_OFF;

#pragma unroll
        for (int s = 0; s < 4; s++) {
            uint32_t af[4][4];
#pragma unroll
            for (int i = 0; i < 4; i++)
                ldsm_x4(af[i], abase + (a_row + i * 16) * ROWB + (s * 2 + a_kc) * 16);
            uint32_t bf[4][2];
#pragma unroll
            for (int jj = 0; jj < 2; jj++) {
                uint32_t r[4];
                uint32_t brow = b_row0 + (2 * jj + b_half) * 8;
                ldsm_x4(r, bbase + brow * ROWB + (s * 2 + b_kc) * 16);
                bf[2 * jj][0] = r[0]; bf[2 * jj][1] = r[1];
                bf[2 * jj + 1][0] = r[2]; bf[2 * jj + 1][1] = r[3];
            }
#pragma unroll
            for (int i = 0; i < 4; i++)
#pragma unroll
                for (int j = 0; j < 4; j++)
                    mma16816(acc[i][j], af[i], bf[j]);
        }
    }

    const int g = lane >> 2, t = lane & 3;
#pragma unroll
    for (int i = 0; i < 4; i++) {
#pragma unroll
        for (int j = 0; j < 4; j++) {
            int row = mbase + wm * 64 + i * 16 + g;
            int col = nbase + wn * 32 + j * 8 + 2 * t;
            *(float2*)&C[(size_t)row * N + col] =
                make_float2(acc[i][j][0], acc[i][j][1]);
            *(float2*)&C[(size_t)(row + 8) * N + col] =
                make_float2(acc[i][j][2], acc[i][j][3]);
        }
    }
}

// ---------------------------------------------------------------------------
// fp32 -> fp16 convert, vectorized: float4 -> 2x half2
// ---------------------------------------------------------------------------
__global__ __launch_bounds__(256) void cvt_kernel(
    const float* __restrict__ X, __half* __restrict__ Y, int total4)
{
    int idx = blockIdx.x * blockDim.x + threadIdx.x;
    if (idx >= total4) return;
    float4 x = ((const float4*)X)[idx];
    __half2* y = (__half2*)Y + 2 * idx;
    y[0] = __floats2half2_rn(x.x, x.y);
    y[1] = __floats2half2_rn(x.z, x.w);
}

// ---------------------------------------------------------------------------
// W [4096, N] -> Bt [N, 4096] fp16 hi, tiled transpose.
// ---------------------------------------------------------------------------
__global__ __launch_bounds__(1024) void tsplit_kernel(
    const float* __restrict__ W, __half* __restrict__ Bt, int N)
{
    __shared__ float t[32][33];
    int n0 = blockIdx.x * 32, k0 = blockIdx.y * 32;
    t[threadIdx.y][threadIdx.x] = W[(size_t)(k0 + threadIdx.y) * N + n0 + threadIdx.x];
    __syncthreads();
    float x = t[threadIdx.x][threadIdx.y];
    int n = n0 + threadIdx.y, k = k0 + threadIdx.x;
    Bt[(size_t)n * KB + k] = __float2half(x);
}

// ---------------------------------------------------------------------------
// RoPE cos/sin table: one thread per (s, j). positions dtype sniffed.
// ---------------------------------------------------------------------------
__global__ __launch_bounds__(256) void rope_table_kernel(const int* __restrict__ pos32)
{
    int idx = blockIdx.x * blockDim.x + threadIdx.x;
    if (idx >= SEQ * 32) return;
    int j = idx & 31, s = idx >> 5;
    bool is64 = (pos32[1] == 0);
    int posi = is64 ? pos32[2 * s] : pos32[s];
    // inv_freq = 10000^(-j/32) = exp2(-j * log2(10000) / 32)
    float inv_freq = exp2f(-(float)j * (13.287712379549449f / 32.0f));
    float fr = (float)posi * inv_freq;
    float cs, sn;
    sincosf(fr, &sn, &cs);
    g_rope[idx] = make_float2(cs, sn);
}

// ---------------------------------------------------------------------------
// Vectorized RoPE + fp16 pack using the table. One thread per output PAIR:
// 64 slots per (s, head): slots 0..31 = rope pair (d, d+32);
// slots 32..63 = passthrough pair (d, d+1) with d = 2*slot (q/k upper half);
// v heads: all 64 slots are passthrough pairs.
// ---------------------------------------------------------------------------
__global__ __launch_bounds__(256) void pack_rope_kernel()
{
    int idx = blockIdx.x * blockDim.x + threadIdx.x;
    if (idx >= SEQ * 48 * 64) return;
    int p  = idx & 63;
    int hh = (idx >> 6) % 48;
    int s  = idx / (48 * 64);
    const float qscale = 0.088388347648318447f;

    if (hh < 40) {
        int base = s * QKVD + ((hh < 32) ? hh * HD : KOFF + (hh - 32) * HD);
        __half* dst = (hh < 32) ? &g_q16[((size_t)hh * SEQ + s) * HD]
                                : &g_k16[((size_t)(hh - 32) * SEQ + s) * HD];
        float sc = (hh < 32) ? qscale : 1.0f;
        if (p < 32) {
            float2 cs = g_rope[s * 32 + p];
            float x1 = g_qkv[base + p];
            float x2 = g_qkv[base + 32 + p];
            dst[p]      = __float2half((x1 * cs.x - x2 * cs.y) * sc);
            dst[p + 32] = __float2half((x2 * cs.x + x1 * cs.y) * sc);
        } else {
            int d = 2 * p;   // 64..126
            float2 v = *(const float2*)&g_qkv[base + d];
            *(__half2*)&dst[d] = __floats2half2_rn(v.x * sc, v.y * sc);
        }
    } else {
        int kvh = hh - 40;
        int d = 2 * p;       // 0..126
        float2 v = *(const float2*)&g_qkv[s * QKVD + VOFF + kvh * HD + d];
        *(__half2*)&g_v16[((size_t)kvh * SEQ + s) * HD + d] = __floats2half2_rn(v.x, v.y);
    }
}

// ---------------------------------------------------------------------------
// Flash attention on mma.sync fp16 (R12 version, passing).
// ---------------------------------------------------------------------------
__global__ __launch_bounds__(256) void attn_mma_kernel()
{
    extern __shared__ char smem[];
    const uint32_t sb = smem_u32(smem);
    const uint32_t Qs = sb;
    const int tid = threadIdx.x, lane = tid & 31, warp = tid >> 5;
    const int g = lane >> 2, t4 = lane & 3;
    const int qt = gridDim.x - 1 - (int)blockIdx.x;
    const int h = blockIdx.y, kvh = h >> 2;
    const int qbase = qt * 128;
    const int qrw = warp * 16;
    const int ntiles = qt * 2 + 2;

    const __half* q16 = g_q16 + (size_t)h   * SEQ * HD;
    const __half* k16 = g_k16 + (size_t)kvh * SEQ * HD;
    const __half* v16 = g_v16 + (size_t)kvh * SEQ * HD;

    auto load_kv = [&](int tt) {
        const int buf = tt % 3;
        const uint32_t Kb = sb + Q_BYTES + buf * (2 * KV_BYTES);
        const uint32_t Vb = Kb + KV_BYTES;
        const int kb = tt * 64;
#pragma unroll
        for (int i = 0; i < 4; i++) {
            int c = tid + 256 * i;
            int row = c >> 4, ch = c & 15;
            CP_ASYNC16(Kb + row * AROW + ch * 16,
                       (const char*)(k16 + (size_t)(kb + row) * HD) + ch * 16);
            CP_ASYNC16(Vb + row * AROW + ch * 16,
                       (const char*)(v16 + (size_t)(kb + row) * HD) + ch * 16);
        }
    };

#pragma unroll
    for (int i = 0; i < 8; i++) {
        int c = tid + 256 * i;
        int row = c >> 4, ch = c & 15;
        CP_ASYNC16(Qs + row * AROW + ch * 16,
                   (const char*)(q16 + (size_t)(qbase + row) * HD) + ch * 16);
    }
    load_kv(0);
    asm volatile("cp.async.commit_group;" ::: "memory");
    load_kv(1);
    asm volatile("cp.async.commit_group;" ::: "memory");

    float of[16][4];
#pragma unroll
    for (int i = 0; i < 16; i++)
#pragma unroll
        for (int r = 0; r < 4; r++) of[i][r] = 0.f;
    float m0 = -INFINITY, m1 = -INFINITY, l0 = 0.f, l1 = 0.f;

    const int row0 = qbase + qrw + g;

    for (int tt = 0; tt < ntiles; tt++) {
        if (tt < ntiles - 1) asm volatile("cp.async.wait_group 1;" ::: "memory");
        else                 asm volatile("cp.async.wait_group 0;" ::: "memory");
        __syncthreads();
        if (tt + 2 < ntiles) {
            load_kv(tt + 2);
            asm volatile("cp.async.commit_group;" ::: "memory");
        }

        const int kb = tt * 64;
        const uint32_t Kb = sb + Q_BYTES + (tt % 3) * (2 * KV_BYTES);
        const uint32_t Vb = Kb + KV_BYTES;

        float sf[8][4];
#pragma unroll
        for (int j = 0; j < 8; j++)
#pragma unroll
            for (int r = 0; r < 4; r++) sf[j][r] = 0.f;
#pragma unroll
        for (int s = 0; s < 8; s++) {
            uint32_t qf[4];
            ldsm_x4(qf, Qs + (qrw + (lane & 15)) * AROW + (s * 2 + (lane >> 4)) * 16);
#pragma unroll
            for (int jj = 0; jj < 4; jj++) {
                uint32_t kr[4];
                int brow = (lane & 7) + (2 * jj + ((lane >> 4) & 1)) * 8;
                ldsm_x4(kr, Kb + brow * AROW + (s * 2 + ((lane >> 3) & 1)) * 16);
                mma16816(sf[2 * jj],     qf, kr);
                mma16816(sf[2 * jj + 1], qf, kr + 2);
            }
        }

        if (kb + 63 > qbase + qrw) {
#pragma unroll
            for (int j = 0; j < 8; j++) {
                int c0 = kb + j * 8 + 2 * t4;
                if (c0     > row0)     sf[j][0] = -INFINITY;
                if (c0 + 1 > row0)     sf[j][1] = -INFINITY;
                if (c0     > row0 + 8) sf[j][2] = -INFINITY;
                if (c0 + 1 > row0 + 8) sf[j][3] = -INFINITY;
            }
        }

        float mt0 = -INFINITY, mt1 = -INFINITY;
#pragma unroll
        for (int j = 0; j < 8; j++) {
            mt0 = fmaxf(mt0, fmaxf(sf[j][0], sf[j][1]));
            mt1 = fmaxf(mt1, fmaxf(sf[j][2], sf[j][3]));
        }
        mt0 = fmaxf(mt0, __shfl_xor_sync(0xffffffffu, mt0, 1));
        mt0 = fmaxf(mt0, __shfl_xor_sync(0xffffffffu, mt0, 2));
        mt1 = fmaxf(mt1, __shfl_xor_sync(0xffffffffu, mt1, 1));
        mt1 = fmaxf(mt1, __shfl_xor_sync(0xffffffffu, mt1, 2));
        float mn0 = fmaxf(m0, mt0), mn1 = fmaxf(m1, mt1);
        float a0 = __expf(m0 - mn0), a1 = __expf(m1 - mn1);
        float s0 = 0.f, s1 = 0.f;
#pragma unroll
        for (int j = 0; j < 8; j++) {
            sf[j][0] = __expf(sf[j][0] - mn0);
            sf[j][1] = __expf(sf[j][1] - mn0);
            sf[j][2] = __expf(sf[j][2] - mn1);
            sf[j][3] = __expf(sf[j][3] - mn1);
            s0 += sf[j][0] + sf[j][1];
            s1 += sf[j][2] + sf[j][3];
        }
        s0 += __shfl_xor_sync(0xffffffffu, s0, 1);
        s0 += __shfl_xor_sync(0xffffffffu, s0, 2);
        s1 += __shfl_xor_sync(0xffffffffu, s1, 1);
        s1 += __shfl_xor_sync(0xffffffffu, s1, 2);
        l0 = l0 * a0 + s0; l1 = l1 * a1 + s1;
        m0 = mn0; m1 = mn1;
#pragma unroll
        for (int i = 0; i < 16; i++) {
            of[i][0] *= a0; of[i][1] *= a0;
            of[i][2] *= a1; of[i][3] *= a1;
        }

#pragma unroll
        for (int c = 0; c < 4; c++) {
            uint32_t af[4];
            af[0] = pack_h2(sf[2 * c][0],     sf[2 * c][1]);
            af[1] = pack_h2(sf[2 * c][2],     sf[2 * c][3]);
            af[2] = pack_h2(sf[2 * c + 1][0], sf[2 * c + 1][1]);
            af[3] = pack_h2(sf[2 * c + 1][2], sf[2 * c + 1][3]);
#pragma unroll
            for (int d2 = 0; d2 < 8; d2++) {
                uint32_t vr[4];
                ldsm_x4t(vr, Vb + (16 * c + (lane & 15)) * AROW
                              + d2 * 32 + ((lane >> 4) & 1) * 16);
                mma16816(of[2 * d2],     af, vr);
                mma16816(of[2 * d2 + 1], af, vr + 2);
            }
        }
    }

    const float inv0 = 1.f / l0, inv1 = 1.f / l1;
#pragma unroll
    for (int dt = 0; dt < 16; dt++) {
        int col = h * HD + dt * 8 + 2 * t4;
        *(__half2*)&g_A2[(size_t)row0 * KB + col] =
            __floats2half2_rn(of[dt][0] * inv0, of[dt][1] * inv0);
        *(__half2*)&g_A2[(size_t)(row0 + 8) * KB + col] =
            __floats2half2_rn(of[dt][2] * inv1, of[dt][3] * inv1);
    }
}

// ---------------------------------------------------------------------------
extern "C" void kernel_launch(void* const* d_in, const int* in_sizes, int n_in,
                              void* d_out, int out_size)
{
    const float* hidden    = (const float*)d_in[0];
    const float* Wqkv      = (const float*)d_in[1];
    const float* Wo        = (const float*)d_in[2];
    const int*   positions = (const int*)d_in[3];
    float*       out       = (float*)d_out;

    float* qkv_ptr;
    __half *A1, *A2, *Bqkv, *Bo;
    cudaGetSymbolAddress((void**)&qkv_ptr, g_qkv);
    cudaGetSymbolAddress((void**)&A1,   g_A1);
    cudaGetSymbolAddress((void**)&A2,   g_A2);
    cudaGetSymbolAddress((void**)&Bqkv, g_Bqkv);
    cudaGetSymbolAddress((void**)&Bo,   g_Bo);

    const int gemm_smem = STAGES * STAGE_BYTES;   // 110592
    cudaFuncSetAttribute(gemm_mma_kernel, cudaFuncAttributeMaxDynamicSharedMemorySize, gemm_smem);
    cudaFuncSetAttribute(attn_mma_kernel, cudaFuncAttributeMaxDynamicSharedMemorySize, ATTN_SMEM);

    // operand conversion + rope table
    cvt_kernel<<<(SEQ * HIDDEN / 4) / 256, 256>>>(hidden, A1, SEQ * HIDDEN / 4);
    tsplit_kernel<<<dim3(QKVD / 32, HIDDEN / 32), dim3(32, 32)>>>(Wqkv, Bqkv, QKVD);
    tsplit_kernel<<<dim3(HIDDEN / 32, HIDDEN / 32), dim3(32, 32)>>>(Wo, Bo, HIDDEN);
    rope_table_kernel<<<(SEQ * 32) / 256, 256>>>(positions);

    // 1) QKV projection (K = 4096)
    gemm_mma_kernel<<<dim3(QKVD / 128, SEQ / 128), 256, gemm_smem>>>(A1, Bqkv, qkv_ptr, QKVD);
    // 2) vectorized RoPE + fp16 pack (table-based, q scaled)
    pack_rope_kernel<<<(SEQ * 48 * 64) / 256, 256>>>();
    // 3) tensor-core flash attention -> g_A2 (fp16)
    attn_mma_kernel<<<dim3(SEQ / 128, NH), 256, ATTN_SMEM>>>();
    // 4) output projection (K = 4096)
    gemm_mma_kernel<<<dim3(HIDDEN / 128, SEQ / 128), 256, gemm_smem>>>(A2, Bo, out, HIDDEN);
}

// round 16
// speedup vs baseline: 2.0016x; 1.1382x over previous
#include <cuda_runtime.h>
#include <cuda_fp16.h>
#include <cstdint>
#include <math.h>

#define SEQ    2048
#define HIDDEN 4096
#define NH     32
#define HD     128
#define NKV    8
#define QKVD   6144
#define KB     4096    // all GEMM operands: fp16, K = 4096
#define BK     64
#define STAGES 3
#define ROWB   144
#define STAGE_BYTES (128 * ROWB * 2)
#define B_OFF  (128 * ROWB)
// attention smem layout: Q + 3 KV buffers
#define AROW   272
#define Q_BYTES (128 * AROW)
#define KV_BYTES (64 * AROW)
#define ATTN_SMEM (Q_BYTES + 3 * (2 * KV_BYTES))  // 139264
// prep kernel block ranges (256 threads each)
#define PREP_CVT (SEQ * HIDDEN / 4 / 256)            // 8192
#define PREP_TSQ ((QKVD / 32) * (HIDDEN / 32))       // 24576
#define PREP_TSO ((HIDDEN / 32) * (HIDDEN / 32))     // 16384
#define PREP_TAB (SEQ * 32 / 256)                    // 256
#define PREP_BLKS (PREP_CVT + PREP_TSQ + PREP_TSO + PREP_TAB)

// ---------------- scratch (__device__ globals; no allocs allowed) ----------
__device__ __half g_A1  [SEQ * KB];
__device__ __half g_A2  [SEQ * KB];
__device__ __half g_Bqkv[QKVD * KB];
__device__ __half g_Bo  [HIDDEN * KB];
__device__ __half g_q16 [NH  * SEQ * HD];
__device__ __half g_k16 [NKV * SEQ * HD];
__device__ __half g_v16 [NKV * SEQ * HD];
__device__ float2 g_rope[SEQ * 32];        // (cos, sin) per (s, j)

__device__ __forceinline__ uint32_t smem_u32(const void* p) {
    uint32_t a;
    asm("{ .reg .u64 t; cvta.to.shared.u64 t, %1; cvt.u32.u64 %0, t; }" : "=r"(a) : "l"(p));
    return a;
}
#define CP_ASYNC16(dst, src) \
    asm volatile("cp.async.cg.shared.global [%0], [%1], 16;" :: "r"(dst), "l"(src) : "memory")

__device__ __forceinline__ void ldsm_x4(uint32_t* r, uint32_t addr) {
    asm volatile("ldmatrix.sync.aligned.m8n8.x4.shared.b16 {%0,%1,%2,%3}, [%4];"
                 : "=r"(r[0]), "=r"(r[1]), "=r"(r[2]), "=r"(r[3]) : "r"(addr));
}
__device__ __forceinline__ void ldsm_x4t(uint32_t* r, uint32_t addr) {
    asm volatile("ldmatrix.sync.aligned.m8n8.x4.trans.shared.b16 {%0,%1,%2,%3}, [%4];"
                 : "=r"(r[0]), "=r"(r[1]), "=r"(r[2]), "=r"(r[3]) : "r"(addr));
}
__device__ __forceinline__ void mma16816(float* d, const uint32_t* a, const uint32_t* b) {
    asm volatile(
        "mma.sync.aligned.m16n8k16.row.col.f32.f16.f16.f32 "
        "{%0,%1,%2,%3}, {%4,%5,%6,%7}, {%8,%9}, {%0,%1,%2,%3};"
        : "+f"(d[0]), "+f"(d[1]), "+f"(d[2]), "+f"(d[3])
        : "r"(a[0]), "r"(a[1]), "r"(a[2]), "r"(a[3]), "r"(b[0]), "r"(b[1]));
}
__device__ __forceinline__ uint32_t pack_h2(float a, float b) {
    __half2 h = __floats2half2_rn(a, b);
    return *(uint32_t*)&h;
}

// ---------------------------------------------------------------------------
// fp16 GEMM: C = A[M,KB] @ Bt[N,KB]^T, 64 k-iterations, BM=BN=128, BK=64,
// 8 warps (2x4, 64x32 tiles), 3-stage lookahead-2 cp.async, 2 CTA/SM.
// mode 0: store C fp32.  mode 1: fused RoPE+scale+fp16 pack epilogue
// (CTA column block == one head) writing g_q16/g_k16/g_v16 directly.
// ---------------------------------------------------------------------------
__global__ __launch_bounds__(256, 2) void gemm_mma_kernel(
    const __half* __restrict__ A,
    const __half* __restrict__ Bt,
    float* __restrict__ C, int N, int mode)
{
    extern __shared__ char smem[];
    const uint32_t sb = smem_u32(smem);
    const int tid = threadIdx.x;
    const int lane = tid & 31, warp = tid >> 5;
    const int wm = warp >> 2, wn = warp & 3;
    const int mbase = blockIdx.y * 128;
    const int nbase = blockIdx.x * 128;
    const int nIter = KB / BK;   // 64

    const __half* Arow = A  + (size_t)mbase * KB;
    const __half* Brow = Bt + (size_t)nbase * KB;

    const int c_row = tid >> 1;
    const int c_ch0 = (tid & 1) * 4;

    auto load_stage = [&](int itL, int stL) {
        const int kb = itL * BK;
        const uint32_t base = sb + stL * STAGE_BYTES;
        const char* asrc = (const char*)(Arow + (size_t)c_row * KB + kb);
        const char* bsrc = (const char*)(Brow + (size_t)c_row * KB + kb);
#pragma unroll
        for (int c = 0; c < 4; c++) {
            int ch = c_ch0 + c;
            CP_ASYNC16(base + c_row * ROWB + ch * 16,         asrc + ch * 16);
            CP_ASYNC16(base + B_OFF + c_row * ROWB + ch * 16, bsrc + ch * 16);
        }
    };

    float acc[4][4][4];
#pragma unroll
    for (int i = 0; i < 4; i++)
#pragma unroll
        for (int j = 0; j < 4; j++)
#pragma unroll
            for (int r = 0; r < 4; r++) acc[i][j][r] = 0.f;

    load_stage(0, 0);
    asm volatile("cp.async.commit_group;" ::: "memory");
    load_stage(1, 1);
    asm volatile("cp.async.commit_group;" ::: "memory");

    const uint32_t a_row = wm * 64 + (lane & 15);
    const uint32_t a_kc  = (lane >> 4);
    const uint32_t b_row0 = wn * 32 + (lane & 7);
    const uint32_t b_half = (lane >> 4) & 1;
    const uint32_t b_kc   = (lane >> 3) & 1;

    for (int it = 0; it < nIter; it++) {
        const int st = it % 3;
        if (it < nIter - 1) asm volatile("cp.async.wait_group 1;" ::: "memory");
        else                asm volatile("cp.async.wait_group 0;" ::: "memory");
        __syncthreads();
        if (it + 2 < nIter) {
            load_stage(it + 2, (it + 2) % 3);
            asm volatile("cp.async.commit_group;" ::: "memory");
        }

        const uint32_t abase = sb + st * STAGE_BYTES;
        const uint32_t bbase = abase + B_OFF;

#pragma unroll
        for (int s = 0; s < 4; s++) {
            uint32_t af[4][4];
#pragma unroll
            for (int i = 0; i < 4; i++)
                ldsm_x4(af[i], abase + (a_row + i * 16) * ROWB + (s * 2 + a_kc) * 16);
            uint32_t bf[4][2];
#pragma unroll
            for (int jj = 0; jj < 2; jj++) {
                uint32_t r[4];
                uint32_t brow = b_row0 + (2 * jj + b_half) * 8;
                ldsm_x4(r, bbase + brow * ROWB + (s * 2 + b_kc) * 16);
                bf[2 * jj][0] = r[0]; bf[2 * jj][1] = r[1];
                bf[2 * jj + 1][0] = r[2]; bf[2 * jj + 1][1] = r[3];
            }
#pragma unroll
            for (int i = 0; i < 4; i++)
#pragma unroll
                for (int j = 0; j < 4; j++)
                    mma16816(acc[i][j], af[i], bf[j]);
        }
    }

    const int g = lane >> 2, t = lane & 3;

    if (mode == 0) {
        // plain fp32 store (output projection)
#pragma unroll
        for (int i = 0; i < 4; i++) {
#pragma unroll
            for (int j = 0; j < 4; j++) {
                int row = mbase + wm * 64 + i * 16 + g;
                int col = nbase + wn * 32 + j * 8 + 2 * t;
                *(float2*)&C[(size_t)row * N + col] =
                    make_float2(acc[i][j][0], acc[i][j][1]);
                *(float2*)&C[(size_t)(row + 8) * N + col] =
                    make_float2(acc[i][j][2], acc[i][j][3]);
            }
        }
        return;
    }

    // mode 1: fused RoPE + scale + fp16 pack. Stage acc tile in smem (fp32).
    __syncthreads();
    float* cs = (float*)smem;   // [128][132]
#pragma unroll
    for (int i = 0; i < 4; i++) {
#pragma unroll
        for (int j = 0; j < 4; j++) {
            int rl = wm * 64 + i * 16 + g;
            int col = wn * 32 + j * 8 + 2 * t;
            *(float2*)&cs[rl * 132 + col] = make_float2(acc[i][j][0], acc[i][j][1]);
            *(float2*)&cs[(rl + 8) * 132 + col] = make_float2(acc[i][j][2], acc[i][j][3]);
        }
    }
    __syncthreads();

    const int hh = nbase >> 7;   // column block == one head
    const bool isv = (hh >= 40);
    const float sc = (hh < 32) ? 0.088388347648318447f : 1.0f;
    __half* dst0;
    if (hh < 32)      dst0 = &g_q16[(size_t)hh * SEQ * HD];
    else if (hh < 40) dst0 = &g_k16[(size_t)(hh - 32) * SEQ * HD];
    else              dst0 = &g_v16[(size_t)(hh - 40) * SEQ * HD];

    for (int ii = tid; ii < 128 * 64; ii += 256) {
        int srow = ii >> 6, p = ii & 63;
        int s = mbase + srow;
        __half* dst = dst0 + (size_t)s * HD;
        if (!isv && p < 32) {
            float2 csn = g_rope[s * 32 + p];
            float x1 = cs[srow * 132 + p];
            float x2 = cs[srow * 132 + 32 + p];
            dst[p]      = __float2half((x1 * csn.x - x2 * csn.y) * sc);
            dst[p + 32] = __float2half((x2 * csn.x + x1 * csn.y) * sc);
        } else {
            int d = 2 * p;                        // 64..126 (q/k) or 0..126 (v)
            float2 v = *(float2*)&cs[srow * 132 + d];
            *(__half2*)&dst[d] = __floats2half2_rn(v.x * sc, v.y * sc);
        }
    }
}

// ---------------------------------------------------------------------------
// Fused prep: [cvt hidden->A1 fp16] + [transpose Wqkv] + [transpose Wo] +
// [rope table]. 256-thread blocks, section dispatch on blockIdx.x.
// ---------------------------------------------------------------------------
__global__ __launch_bounds__(256) void prep_kernel(
    const float* __restrict__ hidden,
    const float* __restrict__ Wqkv,
    const float* __restrict__ Wo,
    const int*   __restrict__ pos32)
{
    __shared__ float t[32][33];
    const int tid = threadIdx.x;
    int b = blockIdx.x;

    if (b < PREP_CVT) {
        int idx = b * 256 + tid;
        float4 x = ((const float4*)hidden)[idx];
        __half2* y = (__half2*)g_A1 + 2 * idx;
        y[0] = __floats2half2_rn(x.x, x.y);
        y[1] = __floats2half2_rn(x.z, x.w);
        return;
    }
    b -= PREP_CVT;
    if (b < PREP_TSQ + PREP_TSO) {
        const float* W;
        __half* Bt;
        int N, bb;
        if (b < PREP_TSQ) { W = Wqkv; Bt = g_Bqkv; N = QKVD; bb = b; }
        else              { W = Wo;   Bt = g_Bo;   N = HIDDEN; bb = b - PREP_TSQ; }
        int n0 = (bb % (N / 32)) * 32;
        int k0 = (bb / (N / 32)) * 32;
        int r = tid >> 3, c4 = (tid & 7) * 4;
        float4 w = *(const float4*)&W[(size_t)(k0 + r) * N + n0 + c4];
        t[r][c4] = w.x; t[r][c4 + 1] = w.y; t[r][c4 + 2] = w.z; t[r][c4 + 3] = w.w;
        __syncthreads();
        int rn = tid >> 3, ck = (tid & 7) * 4;
        __half2 p0 = __floats2half2_rn(t[ck][rn],     t[ck + 1][rn]);
        __half2 p1 = __floats2half2_rn(t[ck + 2][rn], t[ck + 3][rn]);
        *(uint2*)&Bt[(size_t)(n0 + rn) * KB + k0 + ck] =
            make_uint2(*(uint32_t*)&p0, *(uint32_t*)&p1);
        return;
    }
    b -= PREP_TSQ + PREP_TSO;
    {
        int idx = b * 256 + tid;       // (s, j)
        int j = idx & 31, s = idx >> 5;
        bool is64 = (pos32[1] == 0);
        int posi = is64 ? pos32[2 * s] : pos32[s];
        float inv_freq = exp2f(-(float)j * (13.287712379549449f / 32.0f));
        float fr = (float)posi * inv_freq;
        float cssn, sn;
        sincosf(fr, &sn, &cssn);
        g_rope[idx] = make_float2(cssn, sn);
    }
}

// ---------------------------------------------------------------------------
// Flash attention on mma.sync fp16 (R12/R14 version, passing, unchanged).
// ---------------------------------------------------------------------------
__global__ __launch_bounds__(256) void attn_mma_kernel()
{
    extern __shared__ char smem[];
    const uint32_t sb = smem_u32(smem);
    const uint32_t Qs = sb;
    const int tid = threadIdx.x, lane = tid & 31, warp = tid >> 5;
    const int g = lane >> 2, t4 = lane & 3;
    const int qt = gridDim.x - 1 - (int)blockIdx.x;
    const int h = blockIdx.y, kvh = h >> 2;
    const int qbase = qt * 128;
    const int qrw = warp * 16;
    const int ntiles = qt * 2 + 2;

    const __half* q16 = g_q16 + (size_t)h   * SEQ * HD;
    const __half* k16 = g_k16 + (size_t)kvh * SEQ * HD;
    const __half* v16 = g_v16 + (size_t)kvh * SEQ * HD;

    auto load_kv = [&](int tt) {
        const int buf = tt % 3;
        const uint32_t Kb = sb + Q_BYTES + buf * (2 * KV_BYTES);
        const uint32_t Vb = Kb + KV_BYTES;
        const int kb = tt * 64;
#pragma unroll
        for (int i = 0; i < 4; i++) {
            int c = tid + 256 * i;
            int row = c >> 4, ch = c & 15;
            CP_ASYNC16(Kb + row * AROW + ch * 16,
                       (const char*)(k16 + (size_t)(kb + row) * HD) + ch * 16);
            CP_ASYNC16(Vb + row * AROW + ch * 16,
                       (const char*)(v16 + (size_t)(kb + row) * HD) + ch * 16);
        }
    };

#pragma unroll
    for (int i = 0; i < 8; i++) {
        int c = tid + 256 * i;
        int row = c >> 4, ch = c & 15;
        CP_ASYNC16(Qs + row * AROW + ch * 16,
                   (const char*)(q16 + (size_t)(qbase + row) * HD) + ch * 16);
    }
    load_kv(0);
    asm volatile("cp.async.commit_group;" ::: "memory");
    load_kv(1);
    asm volatile("cp.async.commit_group;" ::: "memory");

    float of[16][4];
#pragma unroll
    for (int i = 0; i < 16; i++)
#pragma unroll
        for (int r = 0; r < 4; r++) of[i][r] = 0.f;
    float m0 = -INFINITY, m1 = -INFINITY, l0 = 0.f, l1 = 0.f;

    const int row0 = qbase + qrw + g;

    for (int tt = 0; tt < ntiles; tt++) {
        if (tt < ntiles - 1) asm volatile("cp.async.wait_group 1;" ::: "memory");
        else                 asm volatile("cp.async.wait_group 0;" ::: "memory");
        __syncthreads();
        if (tt + 2 < ntiles) {
            load_kv(tt + 2);
            asm volatile("cp.async.commit_group;" ::: "memory");
        }

        const int kb = tt * 64;
        const uint32_t Kb = sb + Q_BYTES + (tt % 3) * (2 * KV_BYTES);
        const uint32_t Vb = Kb + KV_BYTES;

        float sf[8][4];
#pragma unroll
        for (int j = 0; j < 8; j++)
#pragma unroll
            for (int r = 0; r < 4; r++) sf[j][r] = 0.f;
#pragma unroll
        for (int s = 0; s < 8; s++) {
            uint32_t qf[4];
            ldsm_x4(qf, Qs + (qrw + (lane & 15)) * AROW + (s * 2 + (lane >> 4)) * 16);
#pragma unroll
            for (int jj = 0; jj < 4; jj++) {
                uint32_t kr[4];
                int brow = (lane & 7) + (2 * jj + ((lane >> 4) & 1)) * 8;
                ldsm_x4(kr, Kb + brow * AROW + (s * 2 + ((lane >> 3) & 1)) * 16);
                mma16816(sf[2 * jj],     qf, kr);
                mma16816(sf[2 * jj + 1], qf, kr + 2);
            }
        }

        if (kb + 63 > qbase + qrw) {
#pragma unroll
            for (int j = 0; j < 8; j++) {
                int c0 = kb + j * 8 + 2 * t4;
                if (c0     > row0)     sf[j][0] = -INFINITY;
                if (c0 + 1 > row0)     sf[j][1] = -INFINITY;
                if (c0     > row0 + 8) sf[j][2] = -INFINITY;
                if (c0 + 1 > row0 + 8) sf[j][3] = -INFINITY;
            }
        }

        float mt0 = -INFINITY, mt1 = -INFINITY;
#pragma unroll
        for (int j = 0; j < 8; j++) {
            mt0 = fmaxf(mt0, fmaxf(sf[j][0], sf[j][1]));
            mt1 = fmaxf(mt1, fmaxf(sf[j][2], sf[j][3]));
        }
        mt0 = fmaxf(mt0, __shfl_xor_sync(0xffffffffu, mt0, 1));
        mt0 = fmaxf(mt0, __shfl_xor_sync(0xffffffffu, mt0, 2));
        mt1 = fmaxf(mt1, __shfl_xor_sync(0xffffffffu, mt1, 1));
        mt1 = fmaxf(mt1, __shfl_xor_sync(0xffffffffu, mt1, 2));
        float mn0 = fmaxf(m0, mt0), mn1 = fmaxf(m1, mt1);
        float a0 = __expf(m0 - mn0), a1 = __expf(m1 - mn1);
        float s0 = 0.f, s1 = 0.f;
#pragma unroll
        for (int j = 0; j < 8; j++) {
            sf[j][0] = __expf(sf[j][0] - mn0);
            sf[j][1] = __expf(sf[j][1] - mn0);
            sf[j][2] = __expf(sf[j][2] - mn1);
            sf[j][3] = __expf(sf[j][3] - mn1);
            s0 += sf[j][0] + sf[j][1];
            s1 += sf[j][2] + sf[j][3];
        }
        s0 += __shfl_xor_sync(0xffffffffu, s0, 1);
        s0 += __shfl_xor_sync(0xffffffffu, s0, 2);
        s1 += __shfl_xor_sync(0xffffffffu, s1, 1);
        s1 += __shfl_xor_sync(0xffffffffu, s1, 2);
        l0 = l0 * a0 + s0; l1 = l1 * a1 + s1;
        m0 = mn0; m1 = mn1;
#pragma unroll
        for (int i = 0; i < 16; i++) {
            of[i][0] *= a0; of[i][1] *= a0;
            of[i][2] *= a1; of[i][3] *= a1;
        }

#pragma unroll
        for (int c = 0; c < 4; c++) {
            uint32_t af[4];
            af[0] = pack_h2(sf[2 * c][0],     sf[2 * c][1]);
            af[1] = pack_h2(sf[2 * c][2],     sf[2 * c][3]);
            af[2] = pack_h2(sf[2 * c + 1][0], sf[2 * c + 1][1]);
            af[3] = pack_h2(sf[2 * c + 1][2], sf[2 * c + 1][3]);
#pragma unroll
            for (int d2 = 0; d2 < 8; d2++) {
                uint32_t vr[4];
                ldsm_x4t(vr, Vb + (16 * c + (lane & 15)) * AROW
                              + d2 * 32 + ((lane >> 4) & 1) * 16);
                mma16816(of[2 * d2],     af, vr);
                mma16816(of[2 * d2 + 1], af, vr + 2);
            }
        }
    }

    const float inv0 = 1.f / l0, inv1 = 1.f / l1;
#pragma unroll
    for (int dt = 0; dt < 16; dt++) {
        int col = h * HD + dt * 8 + 2 * t4;
        *(__half2*)&g_A2[(size_t)row0 * KB + col] =
            __floats2half2_rn(of[dt][0] * inv0, of[dt][1] * inv0);
        *(__half2*)&g_A2[(size_t)(row0 + 8) * KB + col] =
            __floats2half2_rn(of[dt][2] * inv1, of[dt][3] * inv1);
    }
}

// ---------------------------------------------------------------------------
extern "C" void kernel_launch(void* const* d_in, const int* in_sizes, int n_in,
                              void* d_out, int out_size)
{
    const float* hidden    = (const float*)d_in[0];
    const float* Wqkv      = (const float*)d_in[1];
    const float* Wo        = (const float*)d_in[2];
    const int*   positions = (const int*)d_in[3];
    float*       out       = (float*)d_out;

    __half *A1, *A2, *Bqkv, *Bo;
    cudaGetSymbolAddress((void**)&A1,   g_A1);
    cudaGetSymbolAddress((void**)&A2,   g_A2);
    cudaGetSymbolAddress((void**)&Bqkv, g_Bqkv);
    cudaGetSymbolAddress((void**)&Bo,   g_Bo);

    const int gemm_smem = STAGES * STAGE_BYTES;   // 110592 (>= 128*132*4 staging)
    cudaFuncSetAttribute(gemm_mma_kernel, cudaFuncAttributeMaxDynamicSharedMemorySize, gemm_smem);
    cudaFuncSetAttribute(attn_mma_kernel, cudaFuncAttributeMaxDynamicSharedMemorySize, ATTN_SMEM);

    // 0) fused prep: cvt + both weight transposes + rope table (one grid)
    prep_kernel<<<PREP_BLKS, 256>>>(hidden, Wqkv, Wo, positions);
    // 1) QKV projection with fused RoPE+pack epilogue -> g_q16/g_k16/g_v16
    gemm_mma_kernel<<<dim3(QKVD / 128, SEQ / 128), 256, gemm_smem>>>(
        A1, Bqkv, nullptr, QKVD, 1);
    // 2) tensor-core flash attention -> g_A2 (fp16)
    attn_mma_kernel<<<dim3(SEQ / 128, NH), 256, ATTN_SMEM>>>();
    // 3) output projection (fp32 store)
    gemm_mma_kernel<<<dim3(HIDDEN / 128, SEQ / 128), 256, gemm_smem>>>(
        A2, Bo, out, HIDDEN, 0);
}

// round 17
// speedup vs baseline: 2.0628x; 1.0306x over previous
#include <cuda_runtime.h>
#include <cuda_fp16.h>
#include <cstdint>
#include <math.h>

#define SEQ    2048
#define HIDDEN 4096
#define NH     32
#define HD     128
#define NKV    8
#define QKVD   6144
#define KB     4096    // all GEMM operands: fp16, K = 4096
#define BK     64
#define STAGES 3
#define ROWB   144
#define STAGE_BYTES (128 * ROWB * 2)
#define B_OFF  (128 * ROWB)
// attention smem layout: Q + 3 KV buffers
#define AROW   272
#define Q_BYTES (128 * AROW)
#define KV_BYTES (64 * AROW)
#define ATTN_SMEM (Q_BYTES + 3 * (2 * KV_BYTES))  // 139264
// prep kernel block ranges (256 threads each): cvt + Wqkv transpose + table
#define PREP_CVT (SEQ * HIDDEN / 4 / 256)            // 8192
#define PREP_TSQ ((QKVD / 32) * (HIDDEN / 32))       // 24576
#define PREP_TAB (SEQ * 32 / 256)                    // 256
#define PREP_BLKS (PREP_CVT + PREP_TSQ + PREP_TAB)
// attention kernel: 512 attn blocks + 512 Wo-transpose blocks (32 tiles each)
#define ATTN_BLKS 512
#define BOT_BLKS  512
#define BOT_TILES_PER_BLK 32   // 512*32 = 16384 = (4096/32)^2

// q scale with log2(e) folded in (softmax runs in exp2 domain)
#define QSCALE (0.088388347648318447f * 1.4426950408889634f)

// ---------------- scratch (__device__ globals; no allocs allowed) ----------
__device__ __half g_A1  [SEQ * KB];
__device__ __half g_A2  [SEQ * KB];
__device__ __half g_Bqkv[QKVD * KB];
__device__ __half g_Bo  [HIDDEN * KB];
__device__ __half g_q16 [NH  * SEQ * HD];
__device__ __half g_k16 [NKV * SEQ * HD];
__device__ __half g_v16 [NKV * SEQ * HD];
__device__ float2 g_rope[SEQ * 32];        // (cos, sin) per (s, j)

__device__ __forceinline__ uint32_t smem_u32(const void* p) {
    uint32_t a;
    asm("{ .reg .u64 t; cvta.to.shared.u64 t, %1; cvt.u32.u64 %0, t; }" : "=r"(a) : "l"(p));
    return a;
}
#define CP_ASYNC16(dst, src) \
    asm volatile("cp.async.cg.shared.global [%0], [%1], 16;" :: "r"(dst), "l"(src) : "memory")

__device__ __forceinline__ void ldsm_x4(uint32_t* r, uint32_t addr) {
    asm volatile("ldmatrix.sync.aligned.m8n8.x4.shared.b16 {%0,%1,%2,%3}, [%4];"
                 : "=r"(r[0]), "=r"(r[1]), "=r"(r[2]), "=r"(r[3]) : "r"(addr));
}
__device__ __forceinline__ void ldsm_x4t(uint32_t* r, uint32_t addr) {
    asm volatile("ldmatrix.sync.aligned.m8n8.x4.trans.shared.b16 {%0,%1,%2,%3}, [%4];"
                 : "=r"(r[0]), "=r"(r[1]), "=r"(r[2]), "=r"(r[3]) : "r"(addr));
}
__device__ __forceinline__ void mma16816(float* d, const uint32_t* a, const uint32_t* b) {
    asm volatile(
        "mma.sync.aligned.m16n8k16.row.col.f32.f16.f16.f32 "
        "{%0,%1,%2,%3}, {%4,%5,%6,%7}, {%8,%9}, {%0,%1,%2,%3};"
        : "+f"(d[0]), "+f"(d[1]), "+f"(d[2]), "+f"(d[3])
        : "r"(a[0]), "r"(a[1]), "r"(a[2]), "r"(a[3]), "r"(b[0]), "r"(b[1]));
}
__device__ __forceinline__ uint32_t pack_h2(float a, float b) {
    __half2 h = __floats2half2_rn(a, b);
    return *(uint32_t*)&h;
}

// ---------------------------------------------------------------------------
// fp16 GEMM: C = A[M,KB] @ Bt[N,KB]^T, 64 k-iterations, BM=BN=128, BK=64,
// 8 warps (2x4, 64x32 tiles), 3-stage lookahead-2 cp.async, 2 CTA/SM.
// mode 0: fp32 C store. mode 1: fused RoPE+scale+fp16 pack epilogue.
// ---------------------------------------------------------------------------
__global__ __launch_bounds__(256, 2) void gemm_mma_kernel(
    const __half* __restrict__ A,
    const __half* __restrict__ Bt,
    float* __restrict__ C, int N, int mode)
{
    extern __shared__ char smem[];
    const uint32_t sb = smem_u32(smem);
    const int tid = threadIdx.x;
    const int lane = tid & 31, warp = tid >> 5;
    const int wm = warp >> 2, wn = warp & 3;
    const int mbase = blockIdx.y * 128;
    const int nbase = blockIdx.x * 128;
    const int nIter = KB / BK;   // 64

    const __half* Arow = A  + (size_t)mbase * KB;
    const __half* Brow = Bt + (size_t)nbase * KB;

    const int c_row = tid >> 1;
    const int c_ch0 = (tid & 1) * 4;

    auto load_stage = [&](int itL, int stL) {
        const int kb = itL * BK;
        const uint32_t base = sb + stL * STAGE_BYTES;
        const char* asrc = (const char*)(Arow + (size_t)c_row * KB + kb);
        const char* bsrc = (const char*)(Brow + (size_t)c_row * KB + kb);
#pragma unroll
        for (int c = 0; c < 4; c++) {
            int ch = c_ch0 + c;
            CP_ASYNC16(base + c_row * ROWB + ch * 16,         asrc + ch * 16);
            CP_ASYNC16(base + B_OFF + c_row * ROWB + ch * 16, bsrc + ch * 16);
        }
    };

    float acc[4][4][4];
#pragma unroll
    for (int i = 0; i < 4; i++)
#pragma unroll
        for (int j = 0; j < 4; j++)
#pragma unroll
            for (int r = 0; r < 4; r++) acc[i][j][r] = 0.f;

    load_stage(0, 0);
    asm volatile("cp.async.commit_group;" ::: "memory");
    load_stage(1, 1);
    asm volatile("cp.async.commit_group;" ::: "memory");

    const uint32_t a_row = wm * 64 + (lane & 15);
    const uint32_t a_kc  = (lane >> 4);
    const uint32_t b_row0 = wn * 32 + (lane & 7);
    const uint32_t b_half = (lane >> 4) & 1;
    const uint32_t b_kc   = (lane >> 3) & 1;

    for (int it = 0; it < nIter; it++) {
        const int st = it % 3;
        if (it < nIter - 1) asm volatile("cp.async.wait_group 1;" ::: "memory");
        else                asm volatile("cp.async.wait_group 0;" ::: "memory");
        __syncthreads();

        const uint32_t abase = sb + st * STAGE_BYTES;
        const uint32_t bbase = abase + B_OFF;

#pragma unroll
        for (int s = 0; s < 4; s++) {
            uint32_t af[4][4];
#pragma unroll
            for (int i = 0; i < 4; i++)
                ldsm_x4(af[i], abase + (a_row + i * 16) * ROWB + (s * 2 + a_kc) * 16);
            uint32_t bf[4][2];
#pragma unroll
            for (int jj = 0; jj < 2; jj++) {
                uint32_t r[4];
                uint32_t brow = b_row0 + (2 * jj + b_half) * 8;
                ldsm_x4(r, bbase + brow * ROWB + (s * 2 + b_kc) * 16);
                bf[2 * jj][0] = r[0]; bf[2 * jj][1] = r[1];
                bf[2 * jj + 1][0] = r[2]; bf[2 * jj + 1][1] = r[3];
            }
            // prefetch tile it+2 after step-0 fragment loads: overlaps MMA phase
            if (s == 0 && it + 2 < nIter) {
                load_stage(it + 2, (it + 2) % 3);
                asm volatile("cp.async.commit_group;" ::: "memory");
            }
#pragma unroll
            for (int i = 0; i < 4; i++)
#pragma unroll
                for (int j = 0; j < 4; j++)
                    mma16816(acc[i][j], af[i], bf[j]);
        }
    }

    const int g = lane >> 2, t = lane & 3;

    if (mode == 0) {
#pragma unroll
        for (int i = 0; i < 4; i++) {
#pragma unroll
            for (int j = 0; j < 4; j++) {
                int row = mbase + wm * 64 + i * 16 + g;
                int col = nbase + wn * 32 + j * 8 + 2 * t;
                *(float2*)&C[(size_t)row * N + col] =
                    make_float2(acc[i][j][0], acc[i][j][1]);
                *(float2*)&C[(size_t)(row + 8) * N + col] =
                    make_float2(acc[i][j][2], acc[i][j][3]);
            }
        }
        return;
    }

    // mode 1: fused RoPE + scale + fp16 pack. Stage acc tile in smem (fp32).
    __syncthreads();
    float* cs = (float*)smem;   // [128][132]
#pragma unroll
    for (int i = 0; i < 4; i++) {
#pragma unroll
        for (int j = 0; j < 4; j++) {
            int rl = wm * 64 + i * 16 + g;
            int col = wn * 32 + j * 8 + 2 * t;
            *(float2*)&cs[rl * 132 + col] = make_float2(acc[i][j][0], acc[i][j][1]);
            *(float2*)&cs[(rl + 8) * 132 + col] = make_float2(acc[i][j][2], acc[i][j][3]);
        }
    }
    __syncthreads();

    const int hh = nbase >> 7;   // column block == one head
    const bool isv = (hh >= 40);
    const float sc = (hh < 32) ? QSCALE : 1.0f;
    __half* dst0;
    if (hh < 32)      dst0 = &g_q16[(size_t)hh * SEQ * HD];
    else if (hh < 40) dst0 = &g_k16[(size_t)(hh - 32) * SEQ * HD];
    else              dst0 = &g_v16[(size_t)(hh - 40) * SEQ * HD];

    for (int ii = tid; ii < 128 * 64; ii += 256) {
        int srow = ii >> 6, p = ii & 63;
        int s = mbase + srow;
        __half* dst = dst0 + (size_t)s * HD;
        if (!isv && p < 32) {
            float2 csn = g_rope[s * 32 + p];
            float x1 = cs[srow * 132 + p];
            float x2 = cs[srow * 132 + 32 + p];
            dst[p]      = __float2half((x1 * csn.x - x2 * csn.y) * sc);
            dst[p + 32] = __float2half((x2 * csn.x + x1 * csn.y) * sc);
        } else {
            int d = 2 * p;
            float2 v = *(float2*)&cs[srow * 132 + d];
            *(__half2*)&dst[d] = __floats2half2_rn(v.x * sc, v.y * sc);
        }
    }
}

// ---------------------------------------------------------------------------
// Fused prep: [cvt hidden->A1 fp16] + [transpose Wqkv] + [rope table].
// ---------------------------------------------------------------------------
__global__ __launch_bounds__(256) void prep_kernel(
    const float* __restrict__ hidden,
    const float* __restrict__ Wqkv,
    const int*   __restrict__ pos32)
{
    __shared__ float t[32][33];
    const int tid = threadIdx.x;
    int b = blockIdx.x;

    if (b < PREP_CVT) {
        int idx = b * 256 + tid;
        float4 x = ((const float4*)hidden)[idx];
        __half2* y = (__half2*)g_A1 + 2 * idx;
        y[0] = __floats2half2_rn(x.x, x.y);
        y[1] = __floats2half2_rn(x.z, x.w);
        return;
    }
    b -= PREP_CVT;
    if (b < PREP_TSQ) {
        int n0 = (b % (QKVD / 32)) * 32;
        int k0 = (b / (QKVD / 32)) * 32;
        int r = tid >> 3, c4 = (tid & 7) * 4;
        float4 w = *(const float4*)&Wqkv[(size_t)(k0 + r) * QKVD + n0 + c4];
        t[r][c4] = w.x; t[r][c4 + 1] = w.y; t[r][c4 + 2] = w.z; t[r][c4 + 3] = w.w;
        __syncthreads();
        int rn = tid >> 3, ck = (tid & 7) * 4;
        __half2 p0 = __floats2half2_rn(t[ck][rn],     t[ck + 1][rn]);
        __half2 p1 = __floats2half2_rn(t[ck + 2][rn], t[ck + 3][rn]);
        *(uint2*)&g_Bqkv[(size_t)(n0 + rn) * KB + k0 + ck] =
            make_uint2(*(uint32_t*)&p0, *(uint32_t*)&p1);
        return;
    }
    b -= PREP_TSQ;
    {
        int idx = b * 256 + tid;       // (s, j)
        int j = idx & 31, s = idx >> 5;
        bool is64 = (pos32[1] == 0);
        int posi = is64 ? pos32[2 * s] : pos32[s];
        float inv_freq = exp2f(-(float)j * (13.287712379549449f / 32.0f));
        float fr = (float)posi * inv_freq;
        float cssn, sn;
        sincosf(fr, &sn, &cssn);
        g_rope[idx] = make_float2(cssn, sn);
    }
}

// ---------------------------------------------------------------------------
// Flash attention (exp2-domain softmax) + trailing Wo-transpose blocks.
// blocks [0, 512): attention (qi = b>>5 reversed, h = b&31).
// blocks [512, 1024): Wo transpose, 32 tiles of 32x32 each.
// ---------------------------------------------------------------------------
__global__ __launch_bounds__(256) void attn_mma_kernel(const float* __restrict__ Wo)
{
    extern __shared__ char smem[];
    const int tid = threadIdx.x;
    const int bid = blockIdx.x;

    if (bid >= ATTN_BLKS) {
        // -------- Wo transpose: 32 tiles per block --------
        float (*t)[33] = (float(*)[33])smem;
        const int chunk = bid - ATTN_BLKS;
        for (int i = 0; i < BOT_TILES_PER_BLK; i++) {
            int tile = chunk * BOT_TILES_PER_BLK + i;
            int n0 = (tile % (HIDDEN / 32)) * 32;
            int k0 = (tile / (HIDDEN / 32)) * 32;
            int r = tid >> 3, c4 = (tid & 7) * 4;
            float4 w = *(const float4*)&Wo[(size_t)(k0 + r) * HIDDEN + n0 + c4];
            t[r][c4] = w.x; t[r][c4 + 1] = w.y; t[r][c4 + 2] = w.z; t[r][c4 + 3] = w.w;
            __syncthreads();
            int rn = tid >> 3, ck = (tid & 7) * 4;
            __half2 p0 = __floats2half2_rn(t[ck][rn],     t[ck + 1][rn]);
            __half2 p1 = __floats2half2_rn(t[ck + 2][rn], t[ck + 3][rn]);
            *(uint2*)&g_Bo[(size_t)(n0 + rn) * KB + k0 + ck] =
                make_uint2(*(uint32_t*)&p0, *(uint32_t*)&p1);
            __syncthreads();
        }
        return;
    }

    // -------- attention --------
    const uint32_t sb = smem_u32(smem);
    const uint32_t Qs = sb;
    const int lane = tid & 31, warp = tid >> 5;
    const int g = lane >> 2, t4 = lane & 3;
    const int h = bid & 31;
    const int qt = 15 - (bid >> 5);       // heavy tiles first
    const int kvh = h >> 2;
    const int qbase = qt * 128;
    const int qrw = warp * 16;
    const int ntiles = qt * 2 + 2;

    const __half* q16 = g_q16 + (size_t)h   * SEQ * HD;
    const __half* k16 = g_k16 + (size_t)kvh * SEQ * HD;
    const __half* v16 = g_v16 + (size_t)kvh * SEQ * HD;

    auto load_kv = [&](int tt) {
        const int buf = tt % 3;
        const uint32_t Kb = sb + Q_BYTES + buf * (2 * KV_BYTES);
        const uint32_t Vb = Kb + KV_BYTES;
        const int kb = tt * 64;
#pragma unroll
        for (int i = 0; i < 4; i++) {
            int c = tid + 256 * i;
            int row = c >> 4, ch = c & 15;
            CP_ASYNC16(Kb + row * AROW + ch * 16,
                       (const char*)(k16 + (size_t)(kb + row) * HD) + ch * 16);
            CP_ASYNC16(Vb + row * AROW + ch * 16,
                       (const char*)(v16 + (size_t)(kb + row) * HD) + ch * 16);
        }
    };

#pragma unroll
    for (int i = 0; i < 8; i++) {
        int c = tid + 256 * i;
        int row = c >> 4, ch = c & 15;
        CP_ASYNC16(Qs + row * AROW + ch * 16,
                   (const char*)(q16 + (size_t)(qbase + row) * HD) + ch * 16);
    }
    load_kv(0);
    asm volatile("cp.async.commit_group;" ::: "memory");
    load_kv(1);
    asm volatile("cp.async.commit_group;" ::: "memory");

    float of[16][4];
#pragma unroll
    for (int i = 0; i < 16; i++)
#pragma unroll
        for (int r = 0; r < 4; r++) of[i][r] = 0.f;
    float m0 = -INFINITY, m1 = -INFINITY, l0 = 0.f, l1 = 0.f;

    const int row0 = qbase + qrw + g;

    for (int tt = 0; tt < ntiles; tt++) {
        if (tt < ntiles - 1) asm volatile("cp.async.wait_group 1;" ::: "memory");
        else                 asm volatile("cp.async.wait_group 0;" ::: "memory");
        __syncthreads();
        if (tt + 2 < ntiles) {
            load_kv(tt + 2);
            asm volatile("cp.async.commit_group;" ::: "memory");
        }

        const int kb = tt * 64;
        const uint32_t Kb = sb + Q_BYTES + (tt % 3) * (2 * KV_BYTES);
        const uint32_t Vb = Kb + KV_BYTES;

        float sf[8][4];
#pragma unroll
        for (int j = 0; j < 8; j++)
#pragma unroll
            for (int r = 0; r < 4; r++) sf[j][r] = 0.f;
#pragma unroll
        for (int s = 0; s < 8; s++) {
            uint32_t qf[4];
            ldsm_x4(qf, Qs + (qrw + (lane & 15)) * AROW + (s * 2 + (lane >> 4)) * 16);
#pragma unroll
            for (int jj = 0; jj < 4; jj++) {
                uint32_t kr[4];
                int brow = (lane & 7) + (2 * jj + ((lane >> 4) & 1)) * 8;
                ldsm_x4(kr, Kb + brow * AROW + (s * 2 + ((lane >> 3) & 1)) * 16);
                mma16816(sf[2 * jj],     qf, kr);
                mma16816(sf[2 * jj + 1], qf, kr + 2);
            }
        }

        if (kb + 63 > qbase + qrw) {
#pragma unroll
            for (int j = 0; j < 8; j++) {
                int c0 = kb + j * 8 + 2 * t4;
                if (c0     > row0)     sf[j][0] = -INFINITY;
                if (c0 + 1 > row0)     sf[j][1] = -INFINITY;
                if (c0     > row0 + 8) sf[j][2] = -INFINITY;
                if (c0 + 1 > row0 + 8) sf[j][3] = -INFINITY;
            }
        }

        float mt0 = -INFINITY, mt1 = -INFINITY;
#pragma unroll
        for (int j = 0; j < 8; j++) {
            mt0 = fmaxf(mt0, fmaxf(sf[j][0], sf[j][1]));
            mt1 = fmaxf(mt1, fmaxf(sf[j][2], sf[j][3]));
        }
        mt0 = fmaxf(mt0, __shfl_xor_sync(0xffffffffu, mt0, 1));
        mt0 = fmaxf(mt0, __shfl_xor_sync(0xffffffffu, mt0, 2));
        mt1 = fmaxf(mt1, __shfl_xor_sync(0xffffffffu, mt1, 1));
        mt1 = fmaxf(mt1, __shfl_xor_sync(0xffffffffu, mt1, 2));
        float mn0 = fmaxf(m0, mt0), mn1 = fmaxf(m1, mt1);
        float a0 = exp2f(m0 - mn0), a1 = exp2f(m1 - mn1);
        float s0 = 0.f, s1 = 0.f;
#pragma unroll
        for (int j = 0; j < 8; j++) {
            sf[j][0] = exp2f(sf[j][0] - mn0);
            sf[j][1] = exp2f(sf[j][1] - mn0);
            sf[j][2] = exp2f(sf[j][2] - mn1);
            sf[j][3] = exp2f(sf[j][3] - mn1);
            s0 += sf[j][0] + sf[j][1];
            s1 += sf[j][2] + sf[j][3];
        }
        s0 += __shfl_xor_sync(0xffffffffu, s0, 1);
        s0 += __shfl_xor_sync(0xffffffffu, s0, 2);
        s1 += __shfl_xor_sync(0xffffffffu, s1, 1);
        s1 += __shfl_xor_sync(0xffffffffu, s1, 2);
        l0 = l0 * a0 + s0; l1 = l1 * a1 + s1;
        m0 = mn0; m1 = mn1;
#pragma unroll
        for (int i = 0; i < 16; i++) {
            of[i][0] *= a0; of[i][1] *= a0;
            of[i][2] *= a1; of[i][3] *= a1;
        }

#pragma unroll
        for (int c = 0; c < 4; c++) {
            uint32_t af[4];
            af[0] = pack_h2(sf[2 * c][0],     sf[2 * c][1]);
            af[1] = pack_h2(sf[2 * c][2],     sf[2 * c][3]);
            af[2] = pack_h2(sf[2 * c + 1][0], sf[2 * c + 1][1]);
            af[3] = pack_h2(sf[2 * c + 1][2], sf[2 * c + 1][3]);
#pragma unroll
            for (int d2 = 0; d2 < 8; d2++) {
                uint32_t vr[4];
                ldsm_x4t(vr, Vb + (16 * c + (lane & 15)) * AROW
                              + d2 * 32 + ((lane >> 4) & 1) * 16);
                mma16816(of[2 * d2],     af, vr);
                mma16816(of[2 * d2 + 1], af, vr + 2);
            }
        }
    }

    const float inv0 = 1.f / l0, inv1 = 1.f / l1;
#pragma unroll
    for (int dt = 0; dt < 16; dt++) {
        int col = h * HD + dt * 8 + 2 * t4;
        *(__half2*)&g_A2[(size_t)row0 * KB + col] =
            __floats2half2_rn(of[dt][0] * inv0, of[dt][1] * inv0);
        *(__half2*)&g_A2[(size_t)(row0 + 8) * KB + col] =
            __floats2half2_rn(of[dt][2] * inv1, of[dt][3] * inv1);
    }
}

// ---------------------------------------------------------------------------
extern "C" void kernel_launch(void* const* d_in, const int* in_sizes, int n_in,
                              void* d_out, int out_size)
{
    const float* hidden    = (const float*)d_in[0];
    const float* Wqkv      = (const float*)d_in[1];
    const float* Wo        = (const float*)d_in[2];
    const int*   positions = (const int*)d_in[3];
    float*       out       = (float*)d_out;

    __half *A1, *A2, *Bqkv, *Bo;
    cudaGetSymbolAddress((void**)&A1,   g_A1);
    cudaGetSymbolAddress((void**)&A2,   g_A2);
    cudaGetSymbolAddress((void**)&Bqkv, g_Bqkv);
    cudaGetSymbolAddress((void**)&Bo,   g_Bo);

    const int gemm_smem = STAGES * STAGE_BYTES;   // 110592
    cudaFuncSetAttribute(gemm_mma_kernel, cudaFuncAttributeMaxDynamicSharedMemorySize, gemm_smem);
    cudaFuncSetAttribute(attn_mma_kernel, cudaFuncAttributeMaxDynamicSharedMemorySize, ATTN_SMEM);

    // 0) fused prep: cvt + Wqkv transpose + rope table
    prep_kernel<<<PREP_BLKS, 256>>>(hidden, Wqkv, positions);
    // 1) QKV projection with fused RoPE+pack epilogue -> g_q16/g_k16/g_v16
    gemm_mma_kernel<<<dim3(QKVD / 128, SEQ / 128), 256, gemm_smem>>>(
        A1, Bqkv, nullptr, QKVD, 1);
    // 2) flash attention (+ Wo transpose absorbed as trailing blocks)
    attn_mma_kernel<<<ATTN_BLKS + BOT_BLKS, 256, ATTN_SMEM>>>(Wo);
    // 3) output projection (fp32 store)
    gemm_mma_kernel<<<dim3(HIDDEN / 128, SEQ / 128), 256, gemm_smem>>>(
        A2, Bo, out, HIDDEN, 0);
}